// round 1
// baseline (speedup 1.0000x reference)
#include <cuda_runtime.h>
#include <cstdint>

// Problem constants
#define B_    8
#define CIN   512
#define COUT  512
#define HW    64
#define KS    3
#define KK    9
#define CKK   (CIN*KK)        // 4608
#define PLANE (HW*HW)         // 4096
#define EPSV  1e-8f

// Conv tiling
#define CI_CHUNK 8
#define TS 16                 // spatial tile 16x16
#define HALO 18
#define XS_PLANE (HALO*HALO)  // 324
#define COT 64                // cout per block

// Scratch (device globals: allocation-free)
__device__ float g_wn[CKK * COUT];      // [ci*9+kk][co]  9.4 MB
__device__ float g_q [COUT * CIN];      // [co][ci]       1 MB
__device__ float g_f [B_ * CIN];        // scale * style/smax
__device__ float g_invd[B_ * COUT];     // 1/demod

#define FMA2(d,a,b) asm("fma.rn.f32x2 %0, %1, %2, %0;" : "+l"(d) : "l"(a), "l"(b))

__device__ __forceinline__ unsigned long long dup2(float v) {
    unsigned long long r;
    asm("mov.b64 %0, {%1, %2};" : "=l"(r) : "f"(v), "f"(v));
    return r;
}
__device__ __forceinline__ void unpack2(unsigned long long v, float& lo, float& hi) {
    asm("mov.b64 {%0, %1}, %2;" : "=f"(lo), "=f"(hi) : "l"(v));
}

// ---------------------------------------------------------------------------
// K1: per-cout weight inf-norm, normalized weight (transposed layout), q
// ---------------------------------------------------------------------------
__global__ void k_prep_w(const float* __restrict__ weight) {
    const int co  = blockIdx.x;
    const int tid = threadIdx.x;
    __shared__ float red[256];
    const float* wrow = weight + co * CKK;

    float m = 0.0f;
    for (int i = tid; i < CKK; i += 256) m = fmaxf(m, fabsf(wrow[i]));
    red[tid] = m;
    __syncthreads();
    for (int s = 128; s > 0; s >>= 1) {
        if (tid < s) red[tid] = fmaxf(red[tid], red[tid + s]);
        __syncthreads();
    }
    const float scale = 1.0f / sqrtf((float)CKK);
    const float inv = scale / red[0];

    for (int ci = tid; ci < CIN; ci += 256) {
        const float* wp = wrow + ci * KK;
        float qs = 0.0f;
#pragma unroll
        for (int kk = 0; kk < KK; ++kk) {
            float v = wp[kk] * inv;
            g_wn[(ci * KK + kk) * COUT + co] = v;
            qs += v * v;
        }
        g_q[co * CIN + ci] = qs;
    }
}

// ---------------------------------------------------------------------------
// K2: style inf-norm -> g_f = scale * style / smax   (1 block, warp per b)
// ---------------------------------------------------------------------------
__global__ void k_prep_s(const float* __restrict__ style) {
    const int b = threadIdx.x >> 5, lane = threadIdx.x & 31;
    float m = 0.0f;
#pragma unroll
    for (int t = 0; t < 16; ++t) m = fmaxf(m, fabsf(style[b * CIN + lane + 32 * t]));
#pragma unroll
    for (int o = 16; o; o >>= 1) m = fmaxf(m, __shfl_xor_sync(~0u, m, o));
    const float inv = (1.0f / sqrtf((float)CKK)) / m;
#pragma unroll
    for (int t = 0; t < 16; ++t) {
        int ci = lane + 32 * t;
        g_f[b * CIN + ci] = style[b * CIN + ci] * inv;
    }
}

// ---------------------------------------------------------------------------
// K3: invdemod[b,co] = rsqrt( (Σ g_f^2 q) * 4608 + EPS )   (block per co)
// ---------------------------------------------------------------------------
__global__ void k_demod() {
    const int co = blockIdx.x;
    const int b = threadIdx.x >> 5, lane = threadIdx.x & 31;
    float s = 0.0f;
#pragma unroll
    for (int t = 0; t < 16; ++t) {
        int ci = lane + 32 * t;
        float f = g_f[b * CIN + ci];
        s += f * f * g_q[co * CIN + ci];
    }
#pragma unroll
    for (int o = 16; o; o >>= 1) s += __shfl_xor_sync(~0u, s, o);
    if (lane == 0) g_invd[b * COUT + co] = rsqrtf(s * (float)CKK + EPSV);
}

// ---------------------------------------------------------------------------
// K4: main conv. Block = 64 cout x 16x16 px for one b. FFMA2 register tile.
// ---------------------------------------------------------------------------
__global__ __launch_bounds__(256, 2) void k_conv(
    const float* __restrict__ x,
    const float* __restrict__ noise,
    const float* __restrict__ bias,
    const float* __restrict__ nsp,
    float* __restrict__ out)
{
    __shared__ __align__(16) float xs[CI_CHUNK * XS_PLANE];   // 10368 B
    __shared__ __align__(16) float ws[CI_CHUNK * KK * COT];   // 18432 B

    const int tid  = threadIdx.x;
    const int ty0  = (blockIdx.x >> 2) * TS;
    const int tx0  = (blockIdx.x & 3) * TS;
    const int coBase = blockIdx.y * COT;
    const int b    = blockIdx.z;

    const int tco = tid >> 5;          // warp id -> cout octet
    const int tpx = tid & 31;
    const int r0  = tpx >> 4;          // 0/1
    const int c0  = tpx & 15;
    const int pbase = r0 * HALO + c0;

    unsigned long long acc[32];
#pragma unroll
    for (int i = 0; i < 32; ++i) acc[i] = 0ull;

    const float* fb = g_f + b * CIN;

    for (int cib = 0; cib < CIN; cib += CI_CHUNK) {
        __syncthreads();
        // load modulated x halo tile: xs[ci][18*18] = x * (scale * s[b,ci])
        for (int idx = tid; idx < CI_CHUNK * XS_PLANE; idx += 256) {
            int ci  = idx / XS_PLANE;
            int pos = idx - ci * XS_PLANE;
            int r = pos / HALO, c = pos - r * HALO;
            int gy = ty0 - 1 + r, gx = tx0 - 1 + c;
            float v = 0.0f;
            if ((unsigned)gy < HW && (unsigned)gx < HW)
                v = x[((b * CIN + cib + ci) * HW + gy) * HW + gx];
            xs[idx] = v * fb[cib + ci];
        }
        // load weight tile: ws[row][64], row = ci*9+kk
        for (int idx = tid; idx < CI_CHUNK * KK * COT; idx += 256) {
            int row = idx >> 6, col = idx & 63;
            ws[idx] = g_wn[(cib * KK + row) * COUT + coBase + col];
        }
        __syncthreads();

#pragma unroll 1
        for (int ci = 0; ci < CI_CHUNK; ++ci) {
            const float* xb = xs + ci * XS_PLANE + pbase;
            const unsigned long long* wb =
                reinterpret_cast<const unsigned long long*>(ws + ci * KK * COT + (tco << 3));
#pragma unroll
            for (int kh = 0; kh < 3; ++kh) {
#pragma unroll
                for (int kw = 0; kw < 3; ++kw) {
                    const unsigned long long* wr = wb + (kh * 3 + kw) * (COT / 2);
                    unsigned long long a0 = wr[0], a1 = wr[1], a2 = wr[2], a3 = wr[3];
                    const float* xp = xb + kh * HALO + kw;
#pragma unroll
                    for (int j = 0; j < 8; ++j) {
                        unsigned long long bx = dup2(xp[2 * HALO * j]);
                        FMA2(acc[0 * 8 + j], a0, bx);
                        FMA2(acc[1 * 8 + j], a1, bx);
                        FMA2(acc[2 * 8 + j], a2, bx);
                        FMA2(acc[3 * 8 + j], a3, bx);
                    }
                }
            }
        }
    }

    // epilogue
    const float nsv = nsp[0];
#pragma unroll
    for (int u2 = 0; u2 < 4; ++u2) {
        const int co = coBase + (tco << 3) + 2 * u2;
        const float id0 = g_invd[b * COUT + co];
        const float id1 = g_invd[b * COUT + co + 1];
        const float bz0 = bias[co], bz1 = bias[co + 1];
        float* o0 = out + (size_t)(b * COUT + co) * PLANE;
#pragma unroll
        for (int j = 0; j < 8; ++j) {
            float lo, hi;
            unpack2(acc[u2 * 8 + j], lo, hi);
            const int y = ty0 + r0 + 2 * j;
            const int xx = tx0 + c0;
            const float nz = noise[b * PLANE + y * HW + xx] * nsv;
            o0[y * HW + xx]         = lo * id0 + bz0 + nz;
            o0[PLANE + y * HW + xx] = hi * id1 + bz1 + nz;
        }
    }
}

// ---------------------------------------------------------------------------
extern "C" void kernel_launch(void* const* d_in, const int* in_sizes, int n_in,
                              void* d_out, int out_size) {
    const float* x      = (const float*)d_in[0];
    const float* style  = (const float*)d_in[1];
    const float* noise  = (const float*)d_in[2];
    const float* weight = (const float*)d_in[3];
    const float* bias   = (const float*)d_in[4];
    const float* nsp    = (const float*)d_in[5];
    float* out          = (float*)d_out;

    k_prep_w<<<COUT, 256>>>(weight);
    k_prep_s<<<1, 256>>>(style);
    k_demod<<<COUT, 256>>>();

    dim3 grid(16, COUT / COT, B_);
    k_conv<<<grid, 256>>>(x, noise, bias, nsp, out);
}

// round 2
// speedup vs baseline: 1.0005x; 1.0005x over previous
#include <cuda_runtime.h>
#include <cstdint>

// Problem constants
#define B_    8
#define CIN   512
#define COUT  512
#define HW    64
#define KS    3
#define KK    9
#define CKK   (CIN*KK)        // 4608
#define PLANE (HW*HW)         // 4096
#define EPSV  1e-8f

// Conv tiling
#define CI_CHUNK 8
#define TS 16                 // spatial tile 16x16
#define HALO 18
#define XS_PLANE (HALO*HALO)  // 324
#define COT 64                // cout per block

// Scratch (device globals: allocation-free)
__device__ float g_wn[CKK * COUT];      // [ci*9+kk][co]  9.4 MB
__device__ float g_q [COUT * CIN];      // [co][ci]       1 MB
__device__ float g_f [B_ * CIN];        // scale * style/smax
__device__ float g_invd[B_ * COUT];     // 1/demod

#define FMA2(d,a,b) asm("fma.rn.f32x2 %0, %1, %2, %0;" : "+l"(d) : "l"(a), "l"(b))

__device__ __forceinline__ unsigned long long dup2(float v) {
    unsigned long long r;
    asm("mov.b64 %0, {%1, %2};" : "=l"(r) : "f"(v), "f"(v));
    return r;
}
__device__ __forceinline__ void unpack2(unsigned long long v, float& lo, float& hi) {
    asm("mov.b64 {%0, %1}, %2;" : "=f"(lo), "=f"(hi) : "l"(v));
}

// ---------------------------------------------------------------------------
// K1: per-cout weight inf-norm, normalized weight (transposed layout), q
// ---------------------------------------------------------------------------
__global__ void k_prep_w(const float* __restrict__ weight) {
    const int co  = blockIdx.x;
    const int tid = threadIdx.x;
    __shared__ float red[256];
    const float* wrow = weight + co * CKK;

    float m = 0.0f;
    for (int i = tid; i < CKK; i += 256) m = fmaxf(m, fabsf(wrow[i]));
    red[tid] = m;
    __syncthreads();
    for (int s = 128; s > 0; s >>= 1) {
        if (tid < s) red[tid] = fmaxf(red[tid], red[tid + s]);
        __syncthreads();
    }
    const float scale = 1.0f / sqrtf((float)CKK);
    const float inv = scale / red[0];

    for (int ci = tid; ci < CIN; ci += 256) {
        const float* wp = wrow + ci * KK;
        float qs = 0.0f;
#pragma unroll
        for (int kk = 0; kk < KK; ++kk) {
            float v = wp[kk] * inv;
            g_wn[(ci * KK + kk) * COUT + co] = v;
            qs += v * v;
        }
        g_q[co * CIN + ci] = qs;
    }
}

// ---------------------------------------------------------------------------
// K2: style inf-norm -> g_f = scale * style / smax   (1 block, warp per b)
// ---------------------------------------------------------------------------
__global__ void k_prep_s(const float* __restrict__ style) {
    const int b = threadIdx.x >> 5, lane = threadIdx.x & 31;
    float m = 0.0f;
#pragma unroll
    for (int t = 0; t < 16; ++t) m = fmaxf(m, fabsf(style[b * CIN + lane + 32 * t]));
#pragma unroll
    for (int o = 16; o; o >>= 1) m = fmaxf(m, __shfl_xor_sync(~0u, m, o));
    const float inv = (1.0f / sqrtf((float)CKK)) / m;
#pragma unroll
    for (int t = 0; t < 16; ++t) {
        int ci = lane + 32 * t;
        g_f[b * CIN + ci] = style[b * CIN + ci] * inv;
    }
}

// ---------------------------------------------------------------------------
// K3: invdemod[b,co] = rsqrt( (Σ g_f^2 q) * 4608 + EPS )   (block per co)
// ---------------------------------------------------------------------------
__global__ void k_demod() {
    const int co = blockIdx.x;
    const int b = threadIdx.x >> 5, lane = threadIdx.x & 31;
    float s = 0.0f;
#pragma unroll
    for (int t = 0; t < 16; ++t) {
        int ci = lane + 32 * t;
        float f = g_f[b * CIN + ci];
        s += f * f * g_q[co * CIN + ci];
    }
#pragma unroll
    for (int o = 16; o; o >>= 1) s += __shfl_xor_sync(~0u, s, o);
    if (lane == 0) g_invd[b * COUT + co] = rsqrtf(s * (float)CKK + EPSV);
}

// ---------------------------------------------------------------------------
// K4: main conv. Block = 64 cout x 16x16 px for one b. FFMA2 register tile.
// ---------------------------------------------------------------------------
__global__ __launch_bounds__(256, 2) void k_conv(
    const float* __restrict__ x,
    const float* __restrict__ noise,
    const float* __restrict__ bias,
    const float* __restrict__ nsp,
    float* __restrict__ out)
{
    __shared__ __align__(16) float xs[CI_CHUNK * XS_PLANE];   // 10368 B
    __shared__ __align__(16) float ws[CI_CHUNK * KK * COT];   // 18432 B

    const int tid  = threadIdx.x;
    const int ty0  = (blockIdx.x >> 2) * TS;
    const int tx0  = (blockIdx.x & 3) * TS;
    const int coBase = blockIdx.y * COT;
    const int b    = blockIdx.z;

    const int tco = tid >> 5;          // warp id -> cout octet
    const int tpx = tid & 31;
    const int r0  = tpx >> 4;          // 0/1
    const int c0  = tpx & 15;
    const int pbase = r0 * HALO + c0;

    unsigned long long acc[32];
#pragma unroll
    for (int i = 0; i < 32; ++i) acc[i] = 0ull;

    const float* fb = g_f + b * CIN;

    for (int cib = 0; cib < CIN; cib += CI_CHUNK) {
        __syncthreads();
        // load modulated x halo tile: xs[ci][18*18] = x * (scale * s[b,ci])
        for (int idx = tid; idx < CI_CHUNK * XS_PLANE; idx += 256) {
            int ci  = idx / XS_PLANE;
            int pos = idx - ci * XS_PLANE;
            int r = pos / HALO, c = pos - r * HALO;
            int gy = ty0 - 1 + r, gx = tx0 - 1 + c;
            float v = 0.0f;
            if ((unsigned)gy < HW && (unsigned)gx < HW)
                v = x[((b * CIN + cib + ci) * HW + gy) * HW + gx];
            xs[idx] = v * fb[cib + ci];
        }
        // load weight tile: ws[row][64], row = ci*9+kk
        for (int idx = tid; idx < CI_CHUNK * KK * COT; idx += 256) {
            int row = idx >> 6, col = idx & 63;
            ws[idx] = g_wn[(cib * KK + row) * COUT + coBase + col];
        }
        __syncthreads();

#pragma unroll 1
        for (int ci = 0; ci < CI_CHUNK; ++ci) {
            const float* xb = xs + ci * XS_PLANE + pbase;
            const unsigned long long* wb =
                reinterpret_cast<const unsigned long long*>(ws + ci * KK * COT + (tco << 3));
#pragma unroll
            for (int kh = 0; kh < 3; ++kh) {
#pragma unroll
                for (int kw = 0; kw < 3; ++kw) {
                    const unsigned long long* wr = wb + (kh * 3 + kw) * (COT / 2);
                    unsigned long long a0 = wr[0], a1 = wr[1], a2 = wr[2], a3 = wr[3];
                    const float* xp = xb + kh * HALO + kw;
#pragma unroll
                    for (int j = 0; j < 8; ++j) {
                        unsigned long long bx = dup2(xp[2 * HALO * j]);
                        FMA2(acc[0 * 8 + j], a0, bx);
                        FMA2(acc[1 * 8 + j], a1, bx);
                        FMA2(acc[2 * 8 + j], a2, bx);
                        FMA2(acc[3 * 8 + j], a3, bx);
                    }
                }
            }
        }
    }

    // epilogue
    const float nsv = nsp[0];
#pragma unroll
    for (int u2 = 0; u2 < 4; ++u2) {
        const int co = coBase + (tco << 3) + 2 * u2;
        const float id0 = g_invd[b * COUT + co];
        const float id1 = g_invd[b * COUT + co + 1];
        const float bz0 = bias[co], bz1 = bias[co + 1];
        float* o0 = out + (size_t)(b * COUT + co) * PLANE;
#pragma unroll
        for (int j = 0; j < 8; ++j) {
            float lo, hi;
            unpack2(acc[u2 * 8 + j], lo, hi);
            const int y = ty0 + r0 + 2 * j;
            const int xx = tx0 + c0;
            const float nz = noise[b * PLANE + y * HW + xx] * nsv;
            o0[y * HW + xx]         = lo * id0 + bz0 + nz;
            o0[PLANE + y * HW + xx] = hi * id1 + bz1 + nz;
        }
    }
}

// ---------------------------------------------------------------------------
extern "C" void kernel_launch(void* const* d_in, const int* in_sizes, int n_in,
                              void* d_out, int out_size) {
    const float* x      = (const float*)d_in[0];
    const float* style  = (const float*)d_in[1];
    const float* noise  = (const float*)d_in[2];
    const float* weight = (const float*)d_in[3];
    const float* bias   = (const float*)d_in[4];
    const float* nsp    = (const float*)d_in[5];
    float* out          = (float*)d_out;

    k_prep_w<<<COUT, 256>>>(weight);
    k_prep_s<<<1, 256>>>(style);
    k_demod<<<COUT, 256>>>();

    dim3 grid(16, COUT / COT, B_);
    k_conv<<<grid, 256>>>(x, noise, bias, nsp, out);
}

// round 6
// speedup vs baseline: 3.3473x; 3.3457x over previous
#include <cuda_runtime.h>
#include <cuda_fp16.h>
#include <cstdint>

#define B_    8
#define CIN   512
#define COUT  512
#define HW    64
#define CKK   4608
#define PLANE 4096
#define EPSV  1e-8f

#define NCHUNK 72            // 8 ci-blocks x 9 kk
#define NT     256           // couts per CTA

// ---- dynamic smem layout (bytes) ----
#define OFF_B    0           // 2 x 32768 (double-buffered B tile: 256 co x 128B)
#define OFF_A    65536       // 16384 (A tile: 128 px x 128B)
#define OFF_SLAB 81920       // 64 ci x 265 f32 = 67840
#define OFF_F    149760      // 512 f32
#define OFF_INVD 151808      // 256 f32
#define OFF_BIAS 152832      // 256 f32
#define SMEM_SZ  153856

// ---- device scratch ----
__device__ unsigned short g_w16[(size_t)COUT * CKK];   // fp16 normalized W [co][kk*512+ci]
__device__ float g_q[COUT * CIN];
__device__ float g_f[B_ * CIN];
__device__ float g_invd[B_ * COUT];

__device__ __forceinline__ uint32_t smem_u32(const void* p) {
    uint32_t a;
    asm("{ .reg .u64 t; cvta.to.shared.u64 t, %1; cvt.u32.u64 %0, t; }" : "=r"(a) : "l"(p));
    return a;
}

#define LDSM4(R, addr)                                                          \
    asm volatile("ldmatrix.sync.aligned.m8n8.x4.shared.b16 {%0,%1,%2,%3}, [%4];"\
        : "=r"((R)[0]), "=r"((R)[1]), "=r"((R)[2]), "=r"((R)[3]) : "r"(addr))
#define MMA16816(D, A, B0, B1)                                                  \
    asm volatile("mma.sync.aligned.m16n8k16.row.col.f32.f16.f16.f32 "           \
        "{%0,%1,%2,%3}, {%4,%5,%6,%7}, {%8,%9}, {%0,%1,%2,%3};"                 \
        : "+f"((D)[0]), "+f"((D)[1]), "+f"((D)[2]), "+f"((D)[3])                \
        : "r"((A)[0]), "r"((A)[1]), "r"((A)[2]), "r"((A)[3]), "r"(B0), "r"(B1))
#define CPA16(dst, src)                                                         \
    asm volatile("cp.async.cg.shared.global [%0], [%1], 16;" :: "r"(dst), "l"(src))
#define CPA_COMMIT() asm volatile("cp.async.commit_group;" ::: "memory")
#define CPA_WAIT0()  asm volatile("cp.async.wait_group 0;" ::: "memory")

// ---------------------------------------------------------------------------
// prep kernels
// ---------------------------------------------------------------------------
__global__ void k_prep_w(const float* __restrict__ weight) {
    const int co = blockIdx.x, tid = threadIdx.x;
    __shared__ float red[256];
    const float* wrow = weight + (size_t)co * CKK;
    float m = 0.0f;
    for (int i = tid; i < CKK; i += 256) m = fmaxf(m, fabsf(wrow[i]));
    red[tid] = m;
    __syncthreads();
    for (int s = 128; s > 0; s >>= 1) {
        if (tid < s) red[tid] = fmaxf(red[tid], red[tid + s]);
        __syncthreads();
    }
    const float inv = (1.0f / sqrtf((float)CKK)) / red[0];
    for (int ci = tid; ci < CIN; ci += 256) {
        float qs = 0.0f;
#pragma unroll
        for (int kk = 0; kk < 9; ++kk) {
            float v = wrow[ci * 9 + kk] * inv;
            g_w16[(size_t)co * CKK + kk * 512 + ci] = __half_as_ushort(__float2half_rn(v));
            qs += v * v;
        }
        g_q[co * CIN + ci] = qs;
    }
}

__global__ void k_prep_s(const float* __restrict__ style) {
    const int b = threadIdx.x >> 5, lane = threadIdx.x & 31;
    float m = 0.0f;
#pragma unroll
    for (int t = 0; t < 16; ++t) m = fmaxf(m, fabsf(style[b * CIN + lane + 32 * t]));
#pragma unroll
    for (int o = 16; o; o >>= 1) m = fmaxf(m, __shfl_xor_sync(~0u, m, o));
    const float inv = (1.0f / sqrtf((float)CKK)) / m;
#pragma unroll
    for (int t = 0; t < 16; ++t) {
        int ci = lane + 32 * t;
        g_f[b * CIN + ci] = style[b * CIN + ci] * inv;
    }
}

__global__ void k_demod() {
    const int co = blockIdx.x;
    const int b = threadIdx.x >> 5, lane = threadIdx.x & 31;
    float s = 0.0f;
#pragma unroll
    for (int t = 0; t < 16; ++t) {
        int ci = lane + 32 * t;
        float f = g_f[b * CIN + ci];
        s += f * f * g_q[co * CIN + ci];
    }
#pragma unroll
    for (int o = 16; o; o >>= 1) s += __shfl_xor_sync(~0u, s, o);
    if (lane == 0) g_invd[b * COUT + co] = rsqrtf(s * (float)CKK + EPSV);
}

// ---------------------------------------------------------------------------
// main conv: fp16 mma.sync implicit GEMM, M128 x N256 x K4608 per CTA
// ---------------------------------------------------------------------------
__global__ __launch_bounds__(256, 1) void k_conv(
    const float* __restrict__ x,
    const float* __restrict__ noise,
    const float* __restrict__ bias,
    const float* __restrict__ nsp,
    float* __restrict__ out)
{
    extern __shared__ char smem[];
    const uint32_t sb = smem_u32(smem);
    const int tid = threadIdx.x;
    const int wid = tid >> 5, lane = tid & 31;
    const int y0 = blockIdx.x * 2;
    const int coBase = blockIdx.y * NT;
    const int b = blockIdx.z;

    float* slab   = (float*)(smem + OFF_SLAB);
    float* f_s    = (float*)(smem + OFF_F);
    float* invd_s = (float*)(smem + OFF_INVD);
    float* bias_s = (float*)(smem + OFF_BIAS);

    for (int i = tid; i < CIN; i += 256) f_s[i] = g_f[b * CIN + i];
    for (int i = tid; i < NT; i += 256) {
        invd_s[i] = g_invd[b * COUT + coBase + i];
        bias_s[i] = bias[coBase + i];
    }

    // ---- issue B tile for chunk 0 ----
    {
        const unsigned short* gsrc = g_w16 + (size_t)coBase * CKK;  // cib=0,kk=0
        const uint32_t Bb = sb + OFF_B;
#pragma unroll
        for (int it = 0; it < 8; ++it) {
            int e = tid + it * 256;
            int r = e >> 3, u = e & 7;
            CPA16(Bb + r * 128 + ((u ^ (r & 7)) << 4), gsrc + (size_t)r * CKK + u * 8);
        }
        CPA_COMMIT();
    }

    float acc[128];
#pragma unroll
    for (int i = 0; i < 128; ++i) acc[i] = 0.0f;

    const int wm = wid & 1, wn = wid >> 1;       // warp grid 2(M) x 4(N)
    const int lr = lane & 15, lc = lane >> 4;
    const uint32_t swm = (uint32_t)((lr & 7) << 4);
    uint32_t aRB[4], bRB[4], kx[4];
#pragma unroll
    for (int t = 0; t < 4; ++t) {
        aRB[t] = sb + OFF_A + (wm * 64 + t * 16 + lr) * 128;
        bRB[t] = (uint32_t)((wn * 64 + t * 16 + lr) * 128);
        kx[t]  = ((uint32_t)(t * 32 + lc * 16)) ^ swm;
    }

    for (int c = 0; c < NCHUNK; ++c) {
        const int cib = c / 9;
        const int kk  = c - cib * 9;
        const int dy = kk / 3, dx = kk - dy * 3;

        __syncthreads();                         // prior readers of A_tile / slab done

        if (kk == 0) {                           // refill x slab for this ci-block
            const int cig0 = cib * 64;
            for (int idx = tid; idx < 64 * 264; idx += 256) {
                int ci = idx / 264;
                int rem = idx - ci * 264;
                int r = rem / 66, cc = rem - r * 66;
                int gy = y0 - 1 + r, gx = cc - 1;
                float v = 0.0f;
                if ((unsigned)gy < HW && (unsigned)gx < HW)
                    v = x[((size_t)(b * CIN + cig0 + ci) * HW + gy) * HW + gx] * f_s[cig0 + ci];
                slab[ci * 265 + rem] = v;
            }
            __syncthreads();
        }

        // ---- build A tile (fp16, swizzled) from slab ----
        {
            const int cp = lane;                 // ci pair index 0..31
            const int base0 = (2 * cp) * 265;
            const int base1 = base0 + 265;
#pragma unroll
            for (int it = 0; it < 16; ++it) {
                int p = wid + it * 8;            // pixel 0..127
                int roff = ((p >> 6) + dy) * 66 + (p & 63) + dx;
                float v0 = slab[base0 + roff];
                float v1 = slab[base1 + roff];
                uint32_t h;
                asm("cvt.rn.f16x2.f32 %0, %1, %2;" : "=r"(h) : "f"(v1), "f"(v0));
                *(uint32_t*)(smem + OFF_A + p * 128 + ((cp * 4) ^ ((p & 7) << 4))) = h;
            }
        }

        CPA_WAIT0();                             // B[c] arrived
        __syncthreads();                         // A + B visible to all

        // ---- prefetch B[c+1] ----
        if (c + 1 < NCHUNK) {
            const int c1 = c + 1;
            const int cib1 = c1 / 9, kk1 = c1 - cib1 * 9;
            const unsigned short* gsrc = g_w16 + (size_t)coBase * CKK + kk1 * 512 + cib1 * 64;
            const uint32_t Bb = sb + OFF_B + (c1 & 1) * 32768;
#pragma unroll
            for (int it = 0; it < 8; ++it) {
                int e = tid + it * 256;
                int r = e >> 3, u = e & 7;
                CPA16(Bb + r * 128 + ((u ^ (r & 7)) << 4), gsrc + (size_t)r * CKK + u * 8);
            }
            CPA_COMMIT();
        }

        // ---- MMA phase: 4 k16 steps ----
        const uint32_t Bb = sb + OFF_B + (c & 1) * 32768;
#pragma unroll
        for (int ks = 0; ks < 4; ++ks) {
            uint32_t af[4][4], bf[4][4];
#pragma unroll
            for (int t = 0; t < 4; ++t) LDSM4(af[t], aRB[t] + kx[ks]);
#pragma unroll
            for (int t = 0; t < 4; ++t) LDSM4(bf[t], Bb + bRB[t] + kx[ks]);
#pragma unroll
            for (int tm = 0; tm < 4; ++tm)
#pragma unroll
                for (int tn = 0; tn < 4; ++tn) {
                    MMA16816(acc + (tm * 8 + tn * 2) * 4,     af[tm], bf[tn][0], bf[tn][2]);
                    MMA16816(acc + (tm * 8 + tn * 2 + 1) * 4, af[tm], bf[tn][1], bf[tn][3]);
                }
        }
    }

    // ---- epilogue ----
    {
        const float nsv = nsp[0];
        const int y = y0 + wm;
        const float* nrow = noise + (size_t)b * PLANE + y * HW;
        float* orow = out + ((size_t)(b * COUT + coBase)) * PLANE + y * HW;
#pragma unroll
        for (int tm = 0; tm < 4; ++tm)
#pragma unroll
            for (int h = 0; h < 2; ++h) {
                const int px = tm * 16 + (lane >> 2) + 8 * h;
                const float nz = nrow[px] * nsv;
#pragma unroll
                for (int tn8 = 0; tn8 < 8; ++tn8) {
                    const int co = wn * 64 + tn8 * 8 + (lane & 3) * 2;
                    const float d0 = acc[(tm * 8 + tn8) * 4 + 2 * h];
                    const float d1 = acc[(tm * 8 + tn8) * 4 + 2 * h + 1];
                    orow[(size_t)co * PLANE + px]       = d0 * invd_s[co]     + bias_s[co]     + nz;
                    orow[(size_t)(co + 1) * PLANE + px] = d1 * invd_s[co + 1] + bias_s[co + 1] + nz;
                }
            }
    }
}

// ---------------------------------------------------------------------------
extern "C" void kernel_launch(void* const* d_in, const int* in_sizes, int n_in,
                              void* d_out, int out_size) {
    const float* x      = (const float*)d_in[0];
    const float* style  = (const float*)d_in[1];
    const float* noise  = (const float*)d_in[2];
    const float* weight = (const float*)d_in[3];
    const float* bias   = (const float*)d_in[4];
    const float* nsp    = (const float*)d_in[5];
    float* out          = (float*)d_out;

    k_prep_w<<<COUT, 256>>>(weight);
    k_prep_s<<<1, 256>>>(style);
    k_demod<<<COUT, 256>>>();

    cudaFuncSetAttribute(k_conv, cudaFuncAttributeMaxDynamicSharedMemorySize, SMEM_SZ);
    dim3 grid(32, 2, B_);
    k_conv<<<grid, 256, SMEM_SZ>>>(x, noise, bias, nsp, out);
}

// round 7
// speedup vs baseline: 3.6189x; 1.0812x over previous
#include <cuda_runtime.h>
#include <cuda_fp16.h>
#include <cstdint>

#define B_    8
#define CIN   512
#define COUT  512
#define HW    64
#define CKK   4608
#define PLANE 4096
#define EPSV  1e-8f

#define NCHUNK 72            // 8 ci-blocks x 9 kk
#define NT     256           // couts per CTA

// ---- dynamic smem layout (bytes) ----
#define OFF_B    0           // 2 x 32768 (double-buffered B tile: 256 co x 128B)
#define OFF_AH   65536       // A halo tile: 264 hp x 64 ci fp16 = 33792
#define OFF_SLAB 99328       // 64 ci x 265 f32 = 67840
#define OFF_F    167168      // 512 f32
#define OFF_INVD 169216      // 256 f32
#define OFF_BIAS 170240      // 256 f32
#define SMEM_SZ  171264

// ---- device scratch ----
__device__ unsigned short g_w16[(size_t)COUT * CKK];   // fp16 normalized W [co][kk*512+ci]
__device__ float g_q[COUT * CIN];
__device__ float g_f[B_ * CIN];
__device__ float g_invd[B_ * COUT];

__device__ __forceinline__ uint32_t smem_u32(const void* p) {
    uint32_t a;
    asm("{ .reg .u64 t; cvta.to.shared.u64 t, %1; cvt.u32.u64 %0, t; }" : "=r"(a) : "l"(p));
    return a;
}

#define LDSM4(R, addr)                                                          \
    asm volatile("ldmatrix.sync.aligned.m8n8.x4.shared.b16 {%0,%1,%2,%3}, [%4];"\
        : "=r"((R)[0]), "=r"((R)[1]), "=r"((R)[2]), "=r"((R)[3]) : "r"(addr))
#define MMA16816(D, A, B0, B1)                                                  \
    asm volatile("mma.sync.aligned.m16n8k16.row.col.f32.f16.f16.f32 "           \
        "{%0,%1,%2,%3}, {%4,%5,%6,%7}, {%8,%9}, {%0,%1,%2,%3};"                 \
        : "+f"((D)[0]), "+f"((D)[1]), "+f"((D)[2]), "+f"((D)[3])                \
        : "r"((A)[0]), "r"((A)[1]), "r"((A)[2]), "r"((A)[3]), "r"(B0), "r"(B1))
#define CPA16(dst, src)                                                         \
    asm volatile("cp.async.cg.shared.global [%0], [%1], 16;" :: "r"(dst), "l"(src))
#define CPA_COMMIT() asm volatile("cp.async.commit_group;" ::: "memory")
#define CPA_WAIT0()  asm volatile("cp.async.wait_group 0;" ::: "memory")
#define CPA_WAIT1()  asm volatile("cp.async.wait_group 1;" ::: "memory")

// ---------------------------------------------------------------------------
// prep kernels
// ---------------------------------------------------------------------------
__global__ void k_prep_w(const float* __restrict__ weight) {
    const int co = blockIdx.x, tid = threadIdx.x;
    __shared__ float red[256];
    const float* wrow = weight + (size_t)co * CKK;
    float m = 0.0f;
    for (int i = tid; i < CKK; i += 256) m = fmaxf(m, fabsf(wrow[i]));
    red[tid] = m;
    __syncthreads();
    for (int s = 128; s > 0; s >>= 1) {
        if (tid < s) red[tid] = fmaxf(red[tid], red[tid + s]);
        __syncthreads();
    }
    const float inv = (1.0f / sqrtf((float)CKK)) / red[0];
    for (int ci = tid; ci < CIN; ci += 256) {
        float qs = 0.0f;
#pragma unroll
        for (int kk = 0; kk < 9; ++kk) {
            float v = wrow[ci * 9 + kk] * inv;
            g_w16[(size_t)co * CKK + kk * 512 + ci] = __half_as_ushort(__float2half_rn(v));
            qs += v * v;
        }
        g_q[co * CIN + ci] = qs;
    }
}

__global__ void k_prep_s(const float* __restrict__ style) {
    const int b = threadIdx.x >> 5, lane = threadIdx.x & 31;
    float m = 0.0f;
#pragma unroll
    for (int t = 0; t < 16; ++t) m = fmaxf(m, fabsf(style[b * CIN + lane + 32 * t]));
#pragma unroll
    for (int o = 16; o; o >>= 1) m = fmaxf(m, __shfl_xor_sync(~0u, m, o));
    const float inv = (1.0f / sqrtf((float)CKK)) / m;
#pragma unroll
    for (int t = 0; t < 16; ++t) {
        int ci = lane + 32 * t;
        g_f[b * CIN + ci] = style[b * CIN + ci] * inv;
    }
}

__global__ void k_demod() {
    const int co = blockIdx.x;
    const int b = threadIdx.x >> 5, lane = threadIdx.x & 31;
    float s = 0.0f;
#pragma unroll
    for (int t = 0; t < 16; ++t) {
        int ci = lane + 32 * t;
        float f = g_f[b * CIN + ci];
        s += f * f * g_q[co * CIN + ci];
    }
#pragma unroll
    for (int o = 16; o; o >>= 1) s += __shfl_xor_sync(~0u, s, o);
    if (lane == 0) g_invd[b * COUT + co] = rsqrtf(s * (float)CKK + EPSV);
}

// ---------------------------------------------------------------------------
// main conv: fp16 mma.sync implicit GEMM, hoisted A-halo tile
// ---------------------------------------------------------------------------
__global__ __launch_bounds__(256, 1) void k_conv(
    const float* __restrict__ x,
    const float* __restrict__ noise,
    const float* __restrict__ bias,
    const float* __restrict__ nsp,
    float* __restrict__ out)
{
    extern __shared__ char smem[];
    const uint32_t sb = smem_u32(smem);
    const int tid = threadIdx.x;
    const int wid = tid >> 5, lane = tid & 31;
    const int y0 = blockIdx.x * 2;
    const int coBase = blockIdx.y * NT;
    const int b = blockIdx.z;

    float* slab   = (float*)(smem + OFF_SLAB);
    float* f_s    = (float*)(smem + OFF_F);
    float* invd_s = (float*)(smem + OFF_INVD);
    float* bias_s = (float*)(smem + OFF_BIAS);

    for (int i = tid; i < CIN; i += 256) f_s[i] = g_f[b * CIN + i];
    for (int i = tid; i < NT; i += 256) {
        invd_s[i] = g_invd[b * COUT + coBase + i];
        bias_s[i] = bias[coBase + i];
    }

    // ---- issue B tile for chunk 0 ----
    {
        const unsigned short* gsrc = g_w16 + (size_t)coBase * CKK;  // cib=0,kk=0
        const uint32_t Bb = sb + OFF_B;
#pragma unroll
        for (int it = 0; it < 8; ++it) {
            int e = tid + it * 256;
            int r = e >> 3, u = e & 7;
            CPA16(Bb + r * 128 + ((u ^ (r & 7)) << 4), gsrc + (size_t)r * CKK + u * 8);
        }
        CPA_COMMIT();
    }

    float acc[128];
#pragma unroll
    for (int i = 0; i < 128; ++i) acc[i] = 0.0f;

    const int wm = wid & 1, wn = wid >> 1;       // warp grid 2(M) x 4(N)
    const int lr = lane & 15, lc = lane >> 4;
    uint32_t bRB[4], kxB[4];
#pragma unroll
    for (int t = 0; t < 4; ++t) {
        bRB[t] = (uint32_t)((wn * 64 + t * 16 + lr) * 128);
        kxB[t] = ((uint32_t)(t * 32 + lc * 16)) ^ ((uint32_t)((lr & 7) << 4));
    }

    for (int c = 0; c < NCHUNK; ++c) {
        const int cib = c / 9;
        const int kk  = c - cib * 9;
        const int dy = kk / 3, dx = kk - dy * 3;

        if (kk == 0) {
            __syncthreads();                     // MMA[c-1] done with A halo + slab
            // ---- refill modulated x slab (fp32, coalesced) ----
            const int cig0 = cib * 64;
            for (int idx = tid; idx < 64 * 264; idx += 256) {
                int ci = idx / 264;
                int rem = idx - ci * 264;
                int r = rem / 66, cc = rem - r * 66;
                int gy = y0 - 1 + r, gx = cc - 1;
                float v = 0.0f;
                if ((unsigned)gy < HW && (unsigned)gx < HW)
                    v = x[((size_t)(b * CIN + cig0 + ci) * HW + gy) * HW + gx] * f_s[cig0 + ci];
                slab[ci * 265 + rem] = v;
            }
            __syncthreads();
            // ---- build fp16 A halo tile once: 264 hp x 64 ci, row-swizzled ----
            {
                const int cp = lane;             // ci-pair index
                const int base0 = (2 * cp) * 265;
                const int base1 = base0 + 265;
#pragma unroll
                for (int it = 0; it < 33; ++it) {
                    int hp = wid + it * 8;       // halo pixel 0..263
                    float v0 = slab[base0 + hp];
                    float v1 = slab[base1 + hp];
                    uint32_t h;
                    asm("cvt.rn.f16x2.f32 %0, %1, %2;" : "=r"(h) : "f"(v1), "f"(v0));
                    *(uint32_t*)(smem + OFF_AH + hp * 128 + ((cp * 4) ^ ((hp & 7) << 4))) = h;
                }
            }
        }

        __syncthreads();                         // prev MMA done (frees B buf being prefetched) / A build done

        // ---- prefetch B[c+1] ----
        if (c + 1 < NCHUNK) {
            const int c1 = c + 1;
            const int cib1 = c1 / 9, kk1 = c1 - cib1 * 9;
            const unsigned short* gsrc = g_w16 + (size_t)coBase * CKK + kk1 * 512 + cib1 * 64;
            const uint32_t Bb = sb + OFF_B + (c1 & 1) * 32768;
#pragma unroll
            for (int it = 0; it < 8; ++it) {
                int e = tid + it * 256;
                int r = e >> 3, u = e & 7;
                CPA16(Bb + r * 128 + ((u ^ (r & 7)) << 4), gsrc + (size_t)r * CKK + u * 8);
            }
            CPA_COMMIT();
            CPA_WAIT1();                         // B[c] arrived (B[c+1] still in flight)
        } else {
            CPA_WAIT0();
        }
        __syncthreads();                         // B[c] visible to all

        // ---- per-kk shifted A row addresses ----
        uint32_t aAddr[4], aSw[4];
#pragma unroll
        for (int t = 0; t < 4; ++t) {
            int hp = (wm + dy) * 66 + t * 16 + lr + dx;
            aAddr[t] = sb + OFF_AH + hp * 128;
            aSw[t]   = (uint32_t)((hp & 7) << 4);
        }
        const uint32_t lcx = (uint32_t)(lc << 4);

        // ---- MMA phase: 4 k16 steps ----
        const uint32_t Bb = sb + OFF_B + (c & 1) * 32768;
#pragma unroll
        for (int ks = 0; ks < 4; ++ks) {
            uint32_t af[4][4], bf[4][4];
            const uint32_t ko = (uint32_t)(ks << 5);
#pragma unroll
            for (int t = 0; t < 4; ++t) LDSM4(af[t], aAddr[t] + ((ko | lcx) ^ aSw[t]));
#pragma unroll
            for (int t = 0; t < 4; ++t) LDSM4(bf[t], Bb + bRB[t] + kxB[ks]);
#pragma unroll
            for (int tm = 0; tm < 4; ++tm)
#pragma unroll
                for (int tn = 0; tn < 4; ++tn) {
                    MMA16816(acc + (tm * 8 + tn * 2) * 4,     af[tm], bf[tn][0], bf[tn][2]);
                    MMA16816(acc + (tm * 8 + tn * 2 + 1) * 4, af[tm], bf[tn][1], bf[tn][3]);
                }
        }
    }

    // ---- epilogue ----
    {
        const float nsv = nsp[0];
        const int y = y0 + wm;
        const float* nrow = noise + (size_t)b * PLANE + y * HW;
        float* orow = out + ((size_t)(b * COUT + coBase)) * PLANE + y * HW;
#pragma unroll
        for (int tm = 0; tm < 4; ++tm)
#pragma unroll
            for (int h = 0; h < 2; ++h) {
                const int px = tm * 16 + (lane >> 2) + 8 * h;
                const float nz = nrow[px] * nsv;
#pragma unroll
                for (int tn8 = 0; tn8 < 8; ++tn8) {
                    const int co = wn * 64 + tn8 * 8 + (lane & 3) * 2;
                    const float d0 = acc[(tm * 8 + tn8) * 4 + 2 * h];
                    const float d1 = acc[(tm * 8 + tn8) * 4 + 2 * h + 1];
                    orow[(size_t)co * PLANE + px]       = d0 * invd_s[co]     + bias_s[co]     + nz;
                    orow[(size_t)(co + 1) * PLANE + px] = d1 * invd_s[co + 1] + bias_s[co + 1] + nz;
                }
            }
    }
}

// ---------------------------------------------------------------------------
extern "C" void kernel_launch(void* const* d_in, const int* in_sizes, int n_in,
                              void* d_out, int out_size) {
    const float* x      = (const float*)d_in[0];
    const float* style  = (const float*)d_in[1];
    const float* noise  = (const float*)d_in[2];
    const float* weight = (const float*)d_in[3];
    const float* bias   = (const float*)d_in[4];
    const float* nsp    = (const float*)d_in[5];
    float* out          = (float*)d_out;

    k_prep_w<<<COUT, 256>>>(weight);
    k_prep_s<<<1, 256>>>(style);
    k_demod<<<COUT, 256>>>();

    cudaFuncSetAttribute(k_conv, cudaFuncAttributeMaxDynamicSharedMemorySize, SMEM_SZ);
    dim3 grid(32, 2, B_);
    k_conv<<<grid, 256, SMEM_SZ>>>(x, noise, bias, nsp, out);
}